// round 15
// baseline (speedup 1.0000x reference)
#include <cuda_runtime.h>
#include <cuda_bf16.h>
#include <cstdint>
#include <math.h>

#define D      4096
#define E      512
#define BROWS  8192
#define NQ     (1ull*BROWS*D)
#define NENC   (1ull*BROWS*E)

#define OUT_Q_OFF    1ull
#define OUT_PERP_OFF (1ull + NQ)
#define OUT_ENC_OFF  (2ull + NQ)

#define MARGIN 4.0f
#define CAP    16

// ---------------- device scratch ----------------
__device__ float              g_cnorm[E];
__device__ __nv_bfloat16      g_Cb[(size_t)E * D];       // 4 MB bf16 codebook
__device__ __nv_bfloat16      g_Xb[(size_t)BROWS * D];   // 64 MB bf16 inputs
__device__ unsigned long long g_best[BROWS];
__device__ unsigned long long g_cand[(size_t)BROWS * CAP];
__device__ int                g_ccnt[BROWS];
__device__ int                g_counts[E];
__device__ double             g_xsum;                    // ||X||_F^2 (exact fp32 path)

#define SWZ128(off) ((off) ^ (((off) >> 3) & 0x70))

__device__ __forceinline__ uint32_t smem_to_u32(const void* p) {
    uint32_t a;
    asm("{ .reg .u64 t; cvta.to.shared.u64 t, %1; cvt.u32.u64 %0, t; }" : "=r"(a) : "l"(p));
    return a;
}

// key packing: monotone float -> u32, argmin with ties -> lowest index
__device__ __forceinline__ unsigned long long make_key(float d, int idx) {
    unsigned int u = __float_as_uint(d);
    u = (u & 0x80000000u) ? ~u : (u | 0x80000000u);
    return ((unsigned long long)u << 32) | (unsigned int)idx;
}
__device__ __forceinline__ float key_to_float(unsigned long long k) {
    unsigned int u = (unsigned int)(k >> 32);
    u = (u & 0x80000000u) ? (u ^ 0x80000000u) : ~u;
    return __uint_as_float(u);
}

// ---------------- init ----------------
__global__ void init_kernel() {
    int i = blockIdx.x * blockDim.x + threadIdx.x;
    if (i < BROWS) { g_best[i] = 0xFFFFFFFFFFFFFFFFull; g_ccnt[i] = 0; }
    if (i < E)     g_counts[i] = 0;
    if (i == 0)    g_xsum = 0.0;
}

// ---------------- X: bf16 convert + exact ||X||^2 (streaming) ----------------
__global__ __launch_bounds__(256)
void convX_kernel(const float* __restrict__ X) {
    const size_t n4 = NQ / 4;                       // 8.4M float4
    const size_t stride = (size_t)gridDim.x * 256;
    float s = 0.f;
    for (size_t i = (size_t)blockIdx.x * 256 + threadIdx.x; i < n4; i += stride) {
        float4 v = ((const float4*)X)[i];
        __nv_bfloat162 lo = __floats2bfloat162_rn(v.x, v.y);
        __nv_bfloat162 hi = __floats2bfloat162_rn(v.z, v.w);
        uint2 p; p.x = *(uint32_t*)&lo; p.y = *(uint32_t*)&hi;
        ((uint2*)g_Xb)[i] = p;
        s += v.x * v.x + v.y * v.y + v.z * v.z + v.w * v.w;
    }
    for (int o = 16; o; o >>= 1) s += __shfl_down_sync(0xffffffffu, s, o);
    __shared__ float ws[8];
    if ((threadIdx.x & 31) == 0) ws[threadIdx.x >> 5] = s;
    __syncthreads();
    if (threadIdx.x == 0) {
        float t = 0.f;
#pragma unroll
        for (int w = 0; w < 8; w++) t += ws[w];
        atomicAdd(&g_xsum, (double)t);
    }
}

// ---------------- codebook: bf16 convert + exact norms ----------------
__global__ __launch_bounds__(128)
void convCnorm_kernel(const float* __restrict__ C) {
    const int e = blockIdx.x;
    const float4* row = (const float4*)(C + (size_t)e * D);
    uint2* brow = (uint2*)(g_Cb + (size_t)e * D);
    float s = 0.f;
#pragma unroll
    for (int i = threadIdx.x; i < D / 4; i += 128) {
        float4 v = row[i];
        __nv_bfloat162 lo = __floats2bfloat162_rn(v.x, v.y);
        __nv_bfloat162 hi = __floats2bfloat162_rn(v.z, v.w);
        uint2 p; p.x = *(uint32_t*)&lo; p.y = *(uint32_t*)&hi;
        brow[i] = p;
        s += v.x * v.x + v.y * v.y + v.z * v.z + v.w * v.w;
    }
    for (int o = 16; o; o >>= 1) s += __shfl_down_sync(0xffffffffu, s, o);
    __shared__ float ws[4];
    if ((threadIdx.x & 31) == 0) ws[threadIdx.x >> 5] = s;
    __syncthreads();
    if (threadIdx.x == 0) g_cnorm[e] = ws[0] + ws[1] + ws[2] + ws[3];
}

// ---------------- mma.sync bf16 GEMM (pure cp.async) + argmin/candidates ----------------
// CTA 256 thr = 8 warps (2M x 4N), tile M=128 x N=256, warp tile 64x64.
// A and B both bf16 in gmem, loaded via cp.async into SW128 smem, double-buffered.
#define TM 128
#define TN 256
#define CH 64
#define NCHUNK (D / CH)
#define A_BYTES 16384
#define B_BYTES 32768
#define GEMM_SMEM (2*A_BYTES + 2*B_BYTES)   // 98304

__global__ __launch_bounds__(256, 1)
void gemm_mma_kernel() {
    extern __shared__ __align__(1024) char smem[];
    const int tid  = threadIdx.x;
    const int lane = tid & 31;
    const int wid  = tid >> 5;
    const int warpM = wid >> 2;
    const int warpN = wid & 3;
    const int rowBase = blockIdx.y * TM;
    const int colBase = blockIdx.x * TN;

    uint32_t sbA[2] = { smem_to_u32(smem),             smem_to_u32(smem) + A_BYTES };
    uint32_t sbB[2] = { smem_to_u32(smem) + 2*A_BYTES, smem_to_u32(smem) + 2*A_BYTES + B_BYTES };

    const __nv_bfloat16* Ag0 = g_Xb + (size_t)rowBase * D;
    const __nv_bfloat16* Cg0 = g_Cb + (size_t)colBase * D;

    // A: 8 thr/row (16B each), rows arow + i*32 (i<4)  -> 1024 transfers
    // B: 8 thr/row (16B each), rows brow + i*32 (i<8)  -> 2048 transfers
    const int arow = tid >> 3, au = tid & 7;
    const int brow = tid >> 3, bu = tid & 7;

    float acc[4][8][4];
#pragma unroll
    for (int mi = 0; mi < 4; mi++)
#pragma unroll
        for (int ni = 0; ni < 8; ni++)
#pragma unroll
            for (int r = 0; r < 4; r++) acc[mi][ni][r] = 0.f;

    // ---- preload chunk 0 (A + B, one commit group) ----
#pragma unroll
    for (int i = 0; i < 4; i++) {
        int r = arow + i * 32;
        uint32_t dst = sbA[0] + SWZ128((uint32_t)(r * 128 + au * 16));
        const __nv_bfloat16* src = Ag0 + (size_t)r * D + au * 8;
        asm volatile("cp.async.cg.shared.global [%0], [%1], 16;" :: "r"(dst), "l"(src));
    }
#pragma unroll
    for (int i = 0; i < 8; i++) {
        int r = brow + i * 32;
        uint32_t dst = sbB[0] + SWZ128((uint32_t)(r * 128 + bu * 16));
        const __nv_bfloat16* src = Cg0 + (size_t)r * D + bu * 8;
        asm volatile("cp.async.cg.shared.global [%0], [%1], 16;" :: "r"(dst), "l"(src));
    }
    asm volatile("cp.async.commit_group;" ::: "memory");

    const int a_r = lane & 15;
    const int a_c = (lane >> 4) * 16;
    const int b_n = ((lane >> 4) << 3) + (lane & 7);
    const int b_c = ((lane >> 3) & 1) * 16;

    for (int kt = 0; kt < NCHUNK; kt++) {
        const int buf = kt & 1;

        asm volatile("cp.async.wait_group 0;" ::: "memory");
        __syncthreads();   // chunk kt visible; all warps done computing kt-1

        // prefetch chunk kt+1 into other buffer (overlaps MMA below)
        if (kt + 1 < NCHUNK) {
            const int nb = buf ^ 1;
            const int k0 = (kt + 1) * CH;
#pragma unroll
            for (int i = 0; i < 4; i++) {
                int r = arow + i * 32;
                uint32_t dst = sbA[nb] + SWZ128((uint32_t)(r * 128 + au * 16));
                const __nv_bfloat16* src = Ag0 + (size_t)r * D + k0 + au * 8;
                asm volatile("cp.async.cg.shared.global [%0], [%1], 16;" :: "r"(dst), "l"(src));
            }
#pragma unroll
            for (int i = 0; i < 8; i++) {
                int r = brow + i * 32;
                uint32_t dst = sbB[nb] + SWZ128((uint32_t)(r * 128 + bu * 16));
                const __nv_bfloat16* src = Cg0 + (size_t)r * D + k0 + bu * 8;
                asm volatile("cp.async.cg.shared.global [%0], [%1], 16;" :: "r"(dst), "l"(src));
            }
            asm volatile("cp.async.commit_group;" ::: "memory");
        }

        // ---- compute chunk kt: 4 k16 steps ----
        const uint32_t aB = sbA[buf], bB = sbB[buf];
#pragma unroll
        for (int kk = 0; kk < 4; kk++) {
            uint32_t af[4][4], bfr[4][4];
#pragma unroll
            for (int mi = 0; mi < 4; mi++) {
                uint32_t addr = aB + SWZ128((uint32_t)((warpM * 64 + mi * 16 + a_r) * 128 + kk * 32 + a_c));
                asm volatile("ldmatrix.sync.aligned.m8n8.x4.shared.b16 {%0,%1,%2,%3}, [%4];"
                    : "=r"(af[mi][0]), "=r"(af[mi][1]), "=r"(af[mi][2]), "=r"(af[mi][3]) : "r"(addr));
            }
#pragma unroll
            for (int ng = 0; ng < 4; ng++) {
                uint32_t addr = bB + SWZ128((uint32_t)((warpN * 64 + ng * 16 + b_n) * 128 + kk * 32 + b_c));
                asm volatile("ldmatrix.sync.aligned.m8n8.x4.shared.b16 {%0,%1,%2,%3}, [%4];"
                    : "=r"(bfr[ng][0]), "=r"(bfr[ng][1]), "=r"(bfr[ng][2]), "=r"(bfr[ng][3]) : "r"(addr));
            }
#pragma unroll
            for (int mi = 0; mi < 4; mi++)
#pragma unroll
                for (int ng = 0; ng < 4; ng++) {
                    asm volatile("mma.sync.aligned.m16n8k16.row.col.f32.bf16.bf16.f32 "
                        "{%0,%1,%2,%3}, {%4,%5,%6,%7}, {%8,%9}, {%0,%1,%2,%3};"
                        : "+f"(acc[mi][2*ng][0]), "+f"(acc[mi][2*ng][1]),
                          "+f"(acc[mi][2*ng][2]), "+f"(acc[mi][2*ng][3])
                        : "r"(af[mi][0]), "r"(af[mi][1]), "r"(af[mi][2]), "r"(af[mi][3]),
                          "r"(bfr[ng][0]), "r"(bfr[ng][1]));
                    asm volatile("mma.sync.aligned.m16n8k16.row.col.f32.bf16.bf16.f32 "
                        "{%0,%1,%2,%3}, {%4,%5,%6,%7}, {%8,%9}, {%0,%1,%2,%3};"
                        : "+f"(acc[mi][2*ng+1][0]), "+f"(acc[mi][2*ng+1][1]),
                          "+f"(acc[mi][2*ng+1][2]), "+f"(acc[mi][2*ng+1][3])
                        : "r"(af[mi][0]), "r"(af[mi][1]), "r"(af[mi][2]), "r"(af[mi][3]),
                          "r"(bfr[ng][2]), "r"(bfr[ng][3]));
                }
        }
    }

    // ---- fused epilogue: per-CTA row argmin + candidate push ----
    __shared__ unsigned long long rowbest[TM];
    for (int i = tid; i < TM; i += 256) rowbest[i] = 0xFFFFFFFFFFFFFFFFull;
    __syncthreads();

    const int g = lane >> 2, t = lane & 3;
#pragma unroll
    for (int mi = 0; mi < 4; mi++) {
#pragma unroll
        for (int rr = 0; rr < 2; rr++) {
            int lrow = warpM * 64 + mi * 16 + rr * 8 + g;
            unsigned long long best = 0xFFFFFFFFFFFFFFFFull;
#pragma unroll
            for (int ni = 0; ni < 8; ni++) {
                int col = colBase + warpN * 64 + ni * 8 + 2 * t;
                float d0 = g_cnorm[col]     - 2.f * acc[mi][ni][rr * 2 + 0];
                float d1 = g_cnorm[col + 1] - 2.f * acc[mi][ni][rr * 2 + 1];
                unsigned long long k0 = make_key(d0, col);
                unsigned long long k1 = make_key(d1, col + 1);
                if (k0 < best) best = k0;
                if (k1 < best) best = k1;
            }
            atomicMin(&rowbest[lrow], best);
        }
    }
    __syncthreads();
    for (int i = tid; i < TM; i += 256)
        atomicMin(&g_best[rowBase + i], rowbest[i]);

#pragma unroll
    for (int mi = 0; mi < 4; mi++) {
#pragma unroll
        for (int rr = 0; rr < 2; rr++) {
            int lrow = warpM * 64 + mi * 16 + rr * 8 + g;
            int grow = rowBase + lrow;
            float thr = key_to_float(rowbest[lrow]) + MARGIN;
#pragma unroll
            for (int ni = 0; ni < 8; ni++) {
                int col = colBase + warpN * 64 + ni * 8 + 2 * t;
                float d0 = g_cnorm[col]     - 2.f * acc[mi][ni][rr * 2 + 0];
                float d1 = g_cnorm[col + 1] - 2.f * acc[mi][ni][rr * 2 + 1];
                if (d0 <= thr) {
                    int p = atomicAdd(&g_ccnt[grow], 1);
                    if (p < CAP) g_cand[(size_t)grow * CAP + p] = make_key(d0, col);
                }
                if (d1 <= thr) {
                    int p = atomicAdd(&g_ccnt[grow], 1);
                    if (p < CAP) g_cand[(size_t)grow * CAP + p] = make_key(d1, col + 1);
                }
            }
        }
    }
}

// ---------------- fused epilogue: resolve idx (+rare exact rescue) + gather/write ----------------
__global__ __launch_bounds__(128)
void epilogue_kernel(const float* __restrict__ X,
                     const float* __restrict__ C,
                     float* __restrict__ out) {
    __shared__ float ws[4];
    __shared__ int   cand[E];
    __shared__ int   ncand;
    __shared__ int   s_idx;

    const int row = blockIdx.x;
    const int tid = threadIdx.x;
    const int lane = tid & 31, wid = tid >> 5;

    const unsigned long long bk = g_best[row];
    const float gd = key_to_float(bk);
    const int gidx = (int)(bk & 0xffffffffull);
    const int cnt = g_ccnt[row];

    if (tid == 0) ncand = 0;
    __syncthreads();
    if (cnt > CAP) {
        for (int i = tid; i < E; i += 128) cand[i] = i;
        if (tid == 0) ncand = E;
    } else if (tid < cnt) {
        unsigned long long k = g_cand[(size_t)row * CAP + tid];
        if (key_to_float(k) <= gd + MARGIN) {
            int p = atomicAdd(&ncand, 1);
            cand[p] = (int)(k & 0xffffffffull);
        }
    }
    __syncthreads();
    const int n = ncand;

    if (n <= 1) {
        if (tid == 0) s_idx = gidx;
    } else {
        const float4* x4 = (const float4*)(X + (size_t)row * D);
        unsigned long long bestE = 0xFFFFFFFFFFFFFFFFull;
        for (int t = 0; t < n; t++) {
            int cidx = cand[t];
            const float4* c4 = (const float4*)(C + (size_t)cidx * D);
            float s = 0.f;
#pragma unroll
            for (int i = tid; i < D / 4; i += 128) {
                float4 xv = x4[i];
                float4 cv = c4[i];
                s += xv.x * cv.x + xv.y * cv.y + xv.z * cv.z + xv.w * cv.w;
            }
            for (int o = 16; o; o >>= 1) s += __shfl_down_sync(0xffffffffu, s, o);
            __syncthreads();
            if (lane == 0) ws[wid] = s;
            __syncthreads();
            if (tid == 0) {
                float dot = ws[0] + ws[1] + ws[2] + ws[3];
                float dist = g_cnorm[cidx] - 2.f * dot;
                unsigned long long kk = make_key(dist, cidx);
                bestE = (kk < bestE) ? kk : bestE;
            }
        }
        if (tid == 0) s_idx = (int)(bestE & 0xffffffffull);
    }
    __syncthreads();
    const int idx = s_idx;
    if (tid == 0) atomicAdd(&g_counts[idx], 1);

    // ---- gather + write (no X): quantized_st == C[idx] to 1 ulp ----
    const float4* c4 = (const float4*)(C + (size_t)idx * D);
    float* qo = out + OUT_Q_OFF + (size_t)row * D;
#pragma unroll
    for (int i = tid; i < D / 4; i += 128) {
        float4 v = c4[i];
        qo[i * 4 + 0] = v.x;
        qo[i * 4 + 1] = v.y;
        qo[i * 4 + 2] = v.z;
        qo[i * 4 + 3] = v.w;
    }

    float* enc = out + OUT_ENC_OFF + (size_t)row * E;
    if (tid == 0) {
        enc[0]   = (idx == 0)   ? 1.f : 0.f;
        enc[1]   = (idx == 1)   ? 1.f : 0.f;
        enc[510] = (idx == 510) ? 1.f : 0.f;
        enc[511] = (idx == 511) ? 1.f : 0.f;
    }
    for (int i = tid; i < 127; i += 128) {
        int kq = 2 + i * 4;
        float4 v = make_float4((idx == kq) ? 1.f : 0.f, (idx == kq + 1) ? 1.f : 0.f,
                               (idx == kq + 2) ? 1.f : 0.f, (idx == kq + 3) ? 1.f : 0.f);
        *(float4*)(enc + kq) = v;
    }
}

// ---------------- scalars: loss from g_best + xsum; perplexity ----------------
__global__ void scalars_kernel(float* __restrict__ out) {
    const int e = threadIdx.x;  // 512 threads
    float p = (float)g_counts[e] / (float)BROWS;
    float term = p * logf(p + 1e-10f);
    float ds = 0.f;
    for (int j = 0; j < 16; j++)
        ds += key_to_float(g_best[e + j * 512]);
    for (int o = 16; o; o >>= 1) {
        term += __shfl_down_sync(0xffffffffu, term, o);
        ds   += __shfl_down_sync(0xffffffffu, ds, o);
    }
    __shared__ float wt[16];
    __shared__ float wd[16];
    if ((e & 31) == 0) { wt[e >> 5] = term; wd[e >> 5] = ds; }
    __syncthreads();
    if (e == 0) {
        float H = 0.f; double DS = 0.0;
        for (int w = 0; w < 16; w++) { H += wt[w]; DS += (double)wd[w]; }
        out[0] = (float)(1.25 * ((g_xsum + DS) / (double)NQ));
        out[OUT_PERP_OFF] = expf(-H);
    }
}

// ---------------- launch ----------------
extern "C" void kernel_launch(void* const* d_in, const int* in_sizes, int n_in,
                              void* d_out, int out_size) {
    const float* X = (const float*)d_in[0];
    const float* C = (const float*)d_in[1];
    if (n_in >= 2 && in_sizes[0] == E * D && in_sizes[1] == BROWS * D) {
        const float* t = X; X = C; C = t;
    }
    float* out = (float*)d_out;

    static bool attr_done = false;
    if (!attr_done) {
        cudaFuncSetAttribute(gemm_mma_kernel,
                             cudaFuncAttributeMaxDynamicSharedMemorySize, GEMM_SMEM);
        attr_done = true;
    }

    init_kernel<<<BROWS / 256, 256>>>();
    convX_kernel<<<296, 256>>>(X);
    convCnorm_kernel<<<E, 128>>>(C);
    dim3 grid(E / TN, BROWS / TM);   // (2, 64)
    gemm_mma_kernel<<<grid, 256, GEMM_SMEM>>>();
    epilogue_kernel<<<BROWS, 128>>>(X, C, out);
    scalars_kernel<<<1, E>>>(out);
}

// round 16
// speedup vs baseline: 1.1548x; 1.1548x over previous
#include <cuda_runtime.h>
#include <cuda_bf16.h>
#include <cstdint>
#include <math.h>

#define D      4096
#define E      512
#define BROWS  8192
#define NQ     (1ull*BROWS*D)
#define NENC   (1ull*BROWS*E)

#define OUT_Q_OFF    1ull
#define OUT_PERP_OFF (1ull + NQ)
#define OUT_ENC_OFF  (2ull + NQ)

#define MARGIN 4.0f
#define CAP    16

// ---------------- device scratch ----------------
__device__ float              g_cnorm[E];
__device__ __nv_bfloat16      g_Cb[(size_t)E * D];       // 4 MB bf16 codebook
__device__ unsigned long long g_best[BROWS];
__device__ unsigned long long g_cand[(size_t)BROWS * CAP];
__device__ int                g_ccnt[BROWS];
__device__ int                g_counts[E];
__device__ double             g_xsum;                    // ||X||_F^2 (exact fp32)

#define SWZ128(off) ((off) ^ (((off) >> 3) & 0x70))

__device__ __forceinline__ uint32_t smem_to_u32(const void* p) {
    uint32_t a;
    asm("{ .reg .u64 t; cvta.to.shared.u64 t, %1; cvt.u32.u64 %0, t; }" : "=r"(a) : "l"(p));
    return a;
}

// key packing: monotone float -> u32, argmin with ties -> lowest index
__device__ __forceinline__ unsigned long long make_key(float d, int idx) {
    unsigned int u = __float_as_uint(d);
    u = (u & 0x80000000u) ? ~u : (u | 0x80000000u);
    return ((unsigned long long)u << 32) | (unsigned int)idx;
}
__device__ __forceinline__ float key_to_float(unsigned long long k) {
    unsigned int u = (unsigned int)(k >> 32);
    u = (u & 0x80000000u) ? (u ^ 0x80000000u) : ~u;
    return __uint_as_float(u);
}

// ---------------- init ----------------
__global__ void init_kernel() {
    int i = blockIdx.x * blockDim.x + threadIdx.x;
    if (i < BROWS) { g_best[i] = 0xFFFFFFFFFFFFFFFFull; g_ccnt[i] = 0; }
    if (i < E)     g_counts[i] = 0;
    if (i == 0)    g_xsum = 0.0;
}

// ---------------- codebook: bf16 convert + exact norms ----------------
__global__ __launch_bounds__(128)
void convCnorm_kernel(const float* __restrict__ C) {
    const int e = blockIdx.x;
    const float4* row = (const float4*)(C + (size_t)e * D);
    uint2* brow = (uint2*)(g_Cb + (size_t)e * D);
    float s = 0.f;
#pragma unroll
    for (int i = threadIdx.x; i < D / 4; i += 128) {
        float4 v = row[i];
        __nv_bfloat162 lo = __floats2bfloat162_rn(v.x, v.y);
        __nv_bfloat162 hi = __floats2bfloat162_rn(v.z, v.w);
        uint2 p; p.x = *(uint32_t*)&lo; p.y = *(uint32_t*)&hi;
        brow[i] = p;
        s += v.x * v.x + v.y * v.y + v.z * v.z + v.w * v.w;
    }
    for (int o = 16; o; o >>= 1) s += __shfl_down_sync(0xffffffffu, s, o);
    __shared__ float ws[4];
    if ((threadIdx.x & 31) == 0) ws[threadIdx.x >> 5] = s;
    __syncthreads();
    if (threadIdx.x == 0) g_cnorm[e] = ws[0] + ws[1] + ws[2] + ws[3];
}

// ---------------- fused: mma.sync bf16 GEMM (128 blocks) + xsum role (64 blocks) ----------------
// GEMM role: R8-proven — CTA 256 thr = 8 warps (2M x 4N), tile M=128 x N=256,
// warp tile 64x64, K chunk 64 bf16 (SW128), double-buffered, inline A convert,
// fused per-row argmin + candidate push.
// xsum role (blocks 128..191): streaming exact fp32 ||X||^2 on the idle SMs.
#define TM 128
#define TN 256
#define CH 64
#define NCHUNK (D / CH)
#define A_BYTES 16384
#define B_BYTES 32768
#define GEMM_SMEM (2*A_BYTES + 2*B_BYTES)   // 98304
#define NGEMM 128
#define NXSUM 64

__global__ __launch_bounds__(256, 1)
void gemm_mma_kernel(const float* __restrict__ X) {
    const int tid  = threadIdx.x;

    // ---------- xsum role ----------
    if (blockIdx.x >= NGEMM) {
        const size_t n4 = NQ / 4;
        const size_t stride = (size_t)NXSUM * 256;
        float s = 0.f;
        for (size_t i = (size_t)(blockIdx.x - NGEMM) * 256 + tid; i < n4; i += stride) {
            float4 v = ((const float4*)X)[i];
            s += v.x * v.x + v.y * v.y + v.z * v.z + v.w * v.w;
        }
        for (int o = 16; o; o >>= 1) s += __shfl_down_sync(0xffffffffu, s, o);
        __shared__ float xws[8];
        if ((tid & 31) == 0) xws[tid >> 5] = s;
        __syncthreads();
        if (tid == 0) {
            float t = 0.f;
#pragma unroll
            for (int w = 0; w < 8; w++) t += xws[w];
            atomicAdd(&g_xsum, (double)t);
        }
        return;
    }

    // ---------- GEMM role ----------
    extern __shared__ __align__(1024) char smem[];
    const int lane = tid & 31;
    const int wid  = tid >> 5;
    const int warpM = wid >> 2;
    const int warpN = wid & 3;
    const int rowBase = (blockIdx.x >> 1) * TM;
    const int colBase = (blockIdx.x & 1) * TN;

    uint32_t sbA[2] = { smem_to_u32(smem),             smem_to_u32(smem) + A_BYTES };
    uint32_t sbB[2] = { smem_to_u32(smem) + 2*A_BYTES, smem_to_u32(smem) + 2*A_BYTES + B_BYTES };
    char* pA[2] = { smem, smem + A_BYTES };

    const float* Xg0 = X + (size_t)rowBase * D;
    const __nv_bfloat16* Cg0 = g_Cb + (size_t)colBase * D;

    const int ar  = tid >> 4, ac4  = tid & 15;   // A: rows ar+i*16
    const int br  = tid >> 3, bc16 = tid & 7;    // B: rows br+i*32

    float acc[4][8][4];
#pragma unroll
    for (int mi = 0; mi < 4; mi++)
#pragma unroll
        for (int ni = 0; ni < 8; ni++)
#pragma unroll
            for (int r = 0; r < 4; r++) acc[mi][ni][r] = 0.f;

    float4 av[8];

    // ---- preload chunk 0 ----
#pragma unroll
    for (int i = 0; i < 8; i++) {
        int r = br + i * 32;
        uint32_t dst = sbB[0] + SWZ128((uint32_t)(r * 128 + bc16 * 16));
        const __nv_bfloat16* src = Cg0 + (size_t)r * D + bc16 * 8;
        asm volatile("cp.async.cg.shared.global [%0], [%1], 16;" :: "r"(dst), "l"(src));
    }
    asm volatile("cp.async.commit_group;" ::: "memory");
#pragma unroll
    for (int i = 0; i < 8; i++)
        av[i] = *(const float4*)(Xg0 + (size_t)(ar + i * 16) * D + ac4 * 4);

    const int a_r = lane & 15;
    const int a_c = (lane >> 4) * 16;
    const int b_n = ((lane >> 4) << 3) + (lane & 7);
    const int b_c = ((lane >> 3) & 1) * 16;

    for (int kt = 0; kt < NCHUNK; kt++) {
        const int buf = kt & 1;

        // STS A (convert fp32 -> bf16, SW128)
#pragma unroll
        for (int i = 0; i < 8; i++) {
            int r = ar + i * 16;
            __nv_bfloat162 lo = __floats2bfloat162_rn(av[i].x, av[i].y);
            __nv_bfloat162 hi = __floats2bfloat162_rn(av[i].z, av[i].w);
            uint2 p; p.x = *(uint32_t*)&lo; p.y = *(uint32_t*)&hi;
            *(uint2*)(pA[buf] + SWZ128((uint32_t)(r * 128 + ac4 * 8))) = p;
        }
        asm volatile("cp.async.wait_group 0;" ::: "memory");
        __syncthreads();

        if (kt + 1 < NCHUNK) {
            const int nb = buf ^ 1;
            const int k0 = (kt + 1) * CH;
#pragma unroll
            for (int i = 0; i < 8; i++) {
                int r = br + i * 32;
                uint32_t dst = sbB[nb] + SWZ128((uint32_t)(r * 128 + bc16 * 16));
                const __nv_bfloat16* src = Cg0 + (size_t)r * D + k0 + bc16 * 8;
                asm volatile("cp.async.cg.shared.global [%0], [%1], 16;" :: "r"(dst), "l"(src));
            }
            asm volatile("cp.async.commit_group;" ::: "memory");
#pragma unroll
            for (int i = 0; i < 8; i++)
                av[i] = *(const float4*)(Xg0 + (size_t)(ar + i * 16) * D + k0 + ac4 * 4);
        }

        const uint32_t aB = sbA[buf], bB = sbB[buf];
#pragma unroll
        for (int kk = 0; kk < 4; kk++) {
            uint32_t af[4][4], bfr[4][4];
#pragma unroll
            for (int mi = 0; mi < 4; mi++) {
                uint32_t addr = aB + SWZ128((uint32_t)((warpM * 64 + mi * 16 + a_r) * 128 + kk * 32 + a_c));
                asm volatile("ldmatrix.sync.aligned.m8n8.x4.shared.b16 {%0,%1,%2,%3}, [%4];"
                    : "=r"(af[mi][0]), "=r"(af[mi][1]), "=r"(af[mi][2]), "=r"(af[mi][3]) : "r"(addr));
            }
#pragma unroll
            for (int ng = 0; ng < 4; ng++) {
                uint32_t addr = bB + SWZ128((uint32_t)((warpN * 64 + ng * 16 + b_n) * 128 + kk * 32 + b_c));
                asm volatile("ldmatrix.sync.aligned.m8n8.x4.shared.b16 {%0,%1,%2,%3}, [%4];"
                    : "=r"(bfr[ng][0]), "=r"(bfr[ng][1]), "=r"(bfr[ng][2]), "=r"(bfr[ng][3]) : "r"(addr));
            }
#pragma unroll
            for (int mi = 0; mi < 4; mi++)
#pragma unroll
                for (int ng = 0; ng < 4; ng++) {
                    asm volatile("mma.sync.aligned.m16n8k16.row.col.f32.bf16.bf16.f32 "
                        "{%0,%1,%2,%3}, {%4,%5,%6,%7}, {%8,%9}, {%0,%1,%2,%3};"
                        : "+f"(acc[mi][2*ng][0]), "+f"(acc[mi][2*ng][1]),
                          "+f"(acc[mi][2*ng][2]), "+f"(acc[mi][2*ng][3])
                        : "r"(af[mi][0]), "r"(af[mi][1]), "r"(af[mi][2]), "r"(af[mi][3]),
                          "r"(bfr[ng][0]), "r"(bfr[ng][1]));
                    asm volatile("mma.sync.aligned.m16n8k16.row.col.f32.bf16.bf16.f32 "
                        "{%0,%1,%2,%3}, {%4,%5,%6,%7}, {%8,%9}, {%0,%1,%2,%3};"
                        : "+f"(acc[mi][2*ng+1][0]), "+f"(acc[mi][2*ng+1][1]),
                          "+f"(acc[mi][2*ng+1][2]), "+f"(acc[mi][2*ng+1][3])
                        : "r"(af[mi][0]), "r"(af[mi][1]), "r"(af[mi][2]), "r"(af[mi][3]),
                          "r"(bfr[ng][2]), "r"(bfr[ng][3]));
                }
        }
    }

    // ---- fused epilogue: per-CTA row argmin + candidate push ----
    __shared__ unsigned long long rowbest[TM];
    for (int i = tid; i < TM; i += 256) rowbest[i] = 0xFFFFFFFFFFFFFFFFull;
    __syncthreads();

    const int g = lane >> 2, t = lane & 3;
#pragma unroll
    for (int mi = 0; mi < 4; mi++) {
#pragma unroll
        for (int rr = 0; rr < 2; rr++) {
            int lrow = warpM * 64 + mi * 16 + rr * 8 + g;
            unsigned long long best = 0xFFFFFFFFFFFFFFFFull;
#pragma unroll
            for (int ni = 0; ni < 8; ni++) {
                int col = colBase + warpN * 64 + ni * 8 + 2 * t;
                float d0 = g_cnorm[col]     - 2.f * acc[mi][ni][rr * 2 + 0];
                float d1 = g_cnorm[col + 1] - 2.f * acc[mi][ni][rr * 2 + 1];
                unsigned long long k0 = make_key(d0, col);
                unsigned long long k1 = make_key(d1, col + 1);
                if (k0 < best) best = k0;
                if (k1 < best) best = k1;
            }
            atomicMin(&rowbest[lrow], best);
        }
    }
    __syncthreads();
    for (int i = tid; i < TM; i += 256)
        atomicMin(&g_best[rowBase + i], rowbest[i]);

#pragma unroll
    for (int mi = 0; mi < 4; mi++) {
#pragma unroll
        for (int rr = 0; rr < 2; rr++) {
            int lrow = warpM * 64 + mi * 16 + rr * 8 + g;
            int grow = rowBase + lrow;
            float thr = key_to_float(rowbest[lrow]) + MARGIN;
#pragma unroll
            for (int ni = 0; ni < 8; ni++) {
                int col = colBase + warpN * 64 + ni * 8 + 2 * t;
                float d0 = g_cnorm[col]     - 2.f * acc[mi][ni][rr * 2 + 0];
                float d1 = g_cnorm[col + 1] - 2.f * acc[mi][ni][rr * 2 + 1];
                if (d0 <= thr) {
                    int p = atomicAdd(&g_ccnt[grow], 1);
                    if (p < CAP) g_cand[(size_t)grow * CAP + p] = make_key(d0, col);
                }
                if (d1 <= thr) {
                    int p = atomicAdd(&g_ccnt[grow], 1);
                    if (p < CAP) g_cand[(size_t)grow * CAP + p] = make_key(d1, col + 1);
                }
            }
        }
    }
}

// ---------------- epilogue: resolve idx (+rare exact rescue) + gather/write ----------------
__global__ __launch_bounds__(128)
void epilogue_kernel(const float* __restrict__ X,
                     const float* __restrict__ C,
                     float* __restrict__ out) {
    __shared__ __align__(16) float q[D];   // 16KB staging for aligned stores
    __shared__ float ws[4];
    __shared__ int   cand[E];
    __shared__ int   ncand;
    __shared__ int   s_idx;

    const int row = blockIdx.x;
    const int tid = threadIdx.x;
    const int lane = tid & 31, wid = tid >> 5;

    const unsigned long long bk = g_best[row];
    const float gd = key_to_float(bk);
    const int gidx = (int)(bk & 0xffffffffull);
    const int cnt = g_ccnt[row];

    if (tid == 0) ncand = 0;
    __syncthreads();
    if (cnt > CAP) {
        for (int i = tid; i < E; i += 128) cand[i] = i;
        if (tid == 0) ncand = E;
    } else if (tid < cnt) {
        unsigned long long k = g_cand[(size_t)row * CAP + tid];
        if (key_to_float(k) <= gd + MARGIN) {
            int p = atomicAdd(&ncand, 1);
            cand[p] = (int)(k & 0xffffffffull);
        }
    }
    __syncthreads();
    const int n = ncand;

    if (n <= 1) {
        if (tid == 0) s_idx = gidx;
    } else {
        // exact rescoring (X read only here; xnorm common -> dropped)
        const float4* x4 = (const float4*)(X + (size_t)row * D);
        unsigned long long bestE = 0xFFFFFFFFFFFFFFFFull;
        for (int t = 0; t < n; t++) {
            int cidx = cand[t];
            const float4* c4 = (const float4*)(C + (size_t)cidx * D);
            float s = 0.f;
#pragma unroll
            for (int i = tid; i < D / 4; i += 128) {
                float4 xv = x4[i];
                float4 cv = c4[i];
                s += xv.x * cv.x + xv.y * cv.y + xv.z * cv.z + xv.w * cv.w;
            }
            for (int o = 16; o; o >>= 1) s += __shfl_down_sync(0xffffffffu, s, o);
            __syncthreads();
            if (lane == 0) ws[wid] = s;
            __syncthreads();
            if (tid == 0) {
                float dot = ws[0] + ws[1] + ws[2] + ws[3];
                float dist = g_cnorm[cidx] - 2.f * dot;
                unsigned long long kk = make_key(dist, cidx);
                bestE = (kk < bestE) ? kk : bestE;
            }
        }
        if (tid == 0) s_idx = (int)(bestE & 0xffffffffull);
    }
    __syncthreads();
    const int idx = s_idx;
    if (tid == 0) atomicAdd(&g_counts[idx], 1);

    // ---- gather C[idx] into smem (aligned), then aligned float4 stores ----
    const float4* c4 = (const float4*)(C + (size_t)idx * D);
#pragma unroll
    for (int i = tid; i < D / 4; i += 128)
        *(float4*)&q[i * 4] = c4[i];
    __syncthreads();

    // quantized_st: base offset 1 -> first 16B-aligned out index at k=3
    float* qo = out + OUT_Q_OFF + (size_t)row * D;
    if (tid == 0) { qo[0] = q[0]; qo[1] = q[1]; qo[2] = q[2]; qo[D - 1] = q[D - 1]; }
#pragma unroll
    for (int i = tid; i < 1023; i += 128) {
        int k = 3 + i * 4;
        *(float4*)(qo + k) = make_float4(q[k], q[k + 1], q[k + 2], q[k + 3]);
    }

    // encodings: base%4==2 -> scalar edges, float4 middle
    float* enc = out + OUT_ENC_OFF + (size_t)row * E;
    if (tid == 0) {
        enc[0]   = (idx == 0)   ? 1.f : 0.f;
        enc[1]   = (idx == 1)   ? 1.f : 0.f;
        enc[510] = (idx == 510) ? 1.f : 0.f;
        enc[511] = (idx == 511) ? 1.f : 0.f;
    }
    for (int i = tid; i < 127; i += 128) {
        int kq = 2 + i * 4;
        float4 v = make_float4((idx == kq) ? 1.f : 0.f, (idx == kq + 1) ? 1.f : 0.f,
                               (idx == kq + 2) ? 1.f : 0.f, (idx == kq + 3) ? 1.f : 0.f);
        *(float4*)(enc + kq) = v;
    }
}

// ---------------- scalars: loss from g_best + xsum; perplexity ----------------
__global__ void scalars_kernel(float* __restrict__ out) {
    const int e = threadIdx.x;  // 512 threads
    float p = (float)g_counts[e] / (float)BROWS;
    float term = p * logf(p + 1e-10f);
    float ds = 0.f;
    for (int j = 0; j < 16; j++)
        ds += key_to_float(g_best[e + j * 512]);
    for (int o = 16; o; o >>= 1) {
        term += __shfl_down_sync(0xffffffffu, term, o);
        ds   += __shfl_down_sync(0xffffffffu, ds, o);
    }
    __shared__ float wt[16];
    __shared__ float wd[16];
    if ((e & 31) == 0) { wt[e >> 5] = term; wd[e >> 5] = ds; }
    __syncthreads();
    if (e == 0) {
        float H = 0.f; double DS = 0.0;
        for (int w = 0; w < 16; w++) { H += wt[w]; DS += (double)wd[w]; }
        out[0] = (float)(1.25 * ((g_xsum + DS) / (double)NQ));
        out[OUT_PERP_OFF] = expf(-H);
    }
}

// ---------------- launch ----------------
extern "C" void kernel_launch(void* const* d_in, const int* in_sizes, int n_in,
                              void* d_out, int out_size) {
    const float* X = (const float*)d_in[0];
    const float* C = (const float*)d_in[1];
    if (n_in >= 2 && in_sizes[0] == E * D && in_sizes[1] == BROWS * D) {
        const float* t = X; X = C; C = t;
    }
    float* out = (float*)d_out;

    static bool attr_done = false;
    if (!attr_done) {
        cudaFuncSetAttribute(gemm_mma_kernel,
                             cudaFuncAttributeMaxDynamicSharedMemorySize, GEMM_SMEM);
        attr_done = true;
    }

    init_kernel<<<BROWS / 256, 256>>>();
    convCnorm_kernel<<<E, 128>>>(C);
    gemm_mma_kernel<<<NGEMM + NXSUM, 256, GEMM_SMEM>>>(X);   // 128 GEMM + 64 xsum blocks
    epilogue_kernel<<<BROWS, 128>>>(X, C, out);
    scalars_kernel<<<1, E>>>(out);
}

// round 17
// speedup vs baseline: 1.2605x; 1.0916x over previous
#include <cuda_runtime.h>
#include <cuda_bf16.h>
#include <cstdint>
#include <math.h>

#define D      4096
#define E      512
#define BROWS  8192
#define NQ     (1ull*BROWS*D)
#define NENC   (1ull*BROWS*E)

#define OUT_Q_OFF    1ull
#define OUT_PERP_OFF (1ull + NQ)
#define OUT_ENC_OFF  (2ull + NQ)

#define MARGIN 4.0f
#define CAP    16

// ---------------- device scratch ----------------
__device__ float              g_cnorm[E];
__device__ __nv_bfloat16      g_Cb[(size_t)E * D];       // 4 MB bf16 codebook
__device__ unsigned long long g_best[BROWS];
__device__ unsigned long long g_cand[(size_t)BROWS * CAP];
__device__ int                g_ccnt[BROWS];
__device__ int                g_counts[E];
__device__ double             g_xsum;                    // ||X||_F^2 (exact fp32)

#define SWZ128(off) ((off) ^ (((off) >> 3) & 0x70))

__device__ __forceinline__ uint32_t smem_to_u32(const void* p) {
    uint32_t a;
    asm("{ .reg .u64 t; cvta.to.shared.u64 t, %1; cvt.u32.u64 %0, t; }" : "=r"(a) : "l"(p));
    return a;
}

// key packing: monotone float -> u32, argmin with ties -> lowest index
__device__ __forceinline__ unsigned long long make_key(float d, int idx) {
    unsigned int u = __float_as_uint(d);
    u = (u & 0x80000000u) ? ~u : (u | 0x80000000u);
    return ((unsigned long long)u << 32) | (unsigned int)idx;
}
__device__ __forceinline__ float key_to_float(unsigned long long k) {
    unsigned int u = (unsigned int)(k >> 32);
    u = (u & 0x80000000u) ? (u ^ 0x80000000u) : ~u;
    return __uint_as_float(u);
}

// ---------------- init ----------------
__global__ void init_kernel() {
    int i = blockIdx.x * blockDim.x + threadIdx.x;
    if (i < BROWS) { g_best[i] = 0xFFFFFFFFFFFFFFFFull; g_ccnt[i] = 0; }
    if (i < E)     g_counts[i] = 0;
    if (i == 0)    g_xsum = 0.0;
}

// ---------------- codebook: bf16 convert + exact norms ----------------
__global__ __launch_bounds__(128)
void convCnorm_kernel(const float* __restrict__ C) {
    const int e = blockIdx.x;
    const float4* row = (const float4*)(C + (size_t)e * D);
    uint2* brow = (uint2*)(g_Cb + (size_t)e * D);
    float s = 0.f;
#pragma unroll
    for (int i = threadIdx.x; i < D / 4; i += 128) {
        float4 v = row[i];
        __nv_bfloat162 lo = __floats2bfloat162_rn(v.x, v.y);
        __nv_bfloat162 hi = __floats2bfloat162_rn(v.z, v.w);
        uint2 p; p.x = *(uint32_t*)&lo; p.y = *(uint32_t*)&hi;
        brow[i] = p;
        s += v.x * v.x + v.y * v.y + v.z * v.z + v.w * v.w;
    }
    for (int o = 16; o; o >>= 1) s += __shfl_down_sync(0xffffffffu, s, o);
    __shared__ float ws[4];
    if ((threadIdx.x & 31) == 0) ws[threadIdx.x >> 5] = s;
    __syncthreads();
    if (threadIdx.x == 0) g_cnorm[e] = ws[0] + ws[1] + ws[2] + ws[3];
}

// ---------------- fused: GEMM (128 blocks) + streaming xsum (20 blocks) = 1 wave ----------------
#define TM 128
#define TN 256
#define CH 64
#define NCHUNK (D / CH)
#define A_BYTES 16384
#define B_BYTES 32768
#define GEMM_SMEM (2*A_BYTES + 2*B_BYTES)   // 98304
#define NGEMM 128
#define NXSUM 20

__global__ __launch_bounds__(256, 1)
void gemm_mma_kernel(const float* __restrict__ X) {
    const int tid  = threadIdx.x;

    // ---------- xsum role (blocks 128..147, the 20 otherwise-idle SMs) ----------
    if (blockIdx.x >= NGEMM) {
        const size_t n4 = NQ / 4;
        const size_t stride = (size_t)NXSUM * 256;
        const float4* xp = (const float4*)X;
        float s = 0.f;
        for (size_t i = (size_t)(blockIdx.x - NGEMM) * 256 + tid; i < n4; i += stride) {
            float4 v = __ldcs(xp + i);   // evict-first: keep codebook in L2
            s += v.x * v.x + v.y * v.y + v.z * v.z + v.w * v.w;
        }
        for (int o = 16; o; o >>= 1) s += __shfl_down_sync(0xffffffffu, s, o);
        __shared__ float xws[8];
        if ((tid & 31) == 0) xws[tid >> 5] = s;
        __syncthreads();
        if (tid == 0) {
            float t = 0.f;
#pragma unroll
            for (int w = 0; w < 8; w++) t += xws[w];
            atomicAdd(&g_xsum, (double)t);
        }
        return;
    }

    // ---------- GEMM role (R8-proven) ----------
    extern __shared__ __align__(1024) char smem[];
    const int lane = tid & 31;
    const int wid  = tid >> 5;
    const int warpM = wid >> 2;
    const int warpN = wid & 3;
    const int rowBase = (blockIdx.x >> 1) * TM;
    const int colBase = (blockIdx.x & 1) * TN;

    uint32_t sbA[2] = { smem_to_u32(smem),             smem_to_u32(smem) + A_BYTES };
    uint32_t sbB[2] = { smem_to_u32(smem) + 2*A_BYTES, smem_to_u32(smem) + 2*A_BYTES + B_BYTES };
    char* pA[2] = { smem, smem + A_BYTES };

    const float* Xg0 = X + (size_t)rowBase * D;
    const __nv_bfloat16* Cg0 = g_Cb + (size_t)colBase * D;

    const int ar  = tid >> 4, ac4  = tid & 15;
    const int br  = tid >> 3, bc16 = tid & 7;

    float acc[4][8][4];
#pragma unroll
    for (int mi = 0; mi < 4; mi++)
#pragma unroll
        for (int ni = 0; ni < 8; ni++)
#pragma unroll
            for (int r = 0; r < 4; r++) acc[mi][ni][r] = 0.f;

    float4 av[8];

#pragma unroll
    for (int i = 0; i < 8; i++) {
        int r = br + i * 32;
        uint32_t dst = sbB[0] + SWZ128((uint32_t)(r * 128 + bc16 * 16));
        const __nv_bfloat16* src = Cg0 + (size_t)r * D + bc16 * 8;
        asm volatile("cp.async.cg.shared.global [%0], [%1], 16;" :: "r"(dst), "l"(src));
    }
    asm volatile("cp.async.commit_group;" ::: "memory");
#pragma unroll
    for (int i = 0; i < 8; i++)
        av[i] = *(const float4*)(Xg0 + (size_t)(ar + i * 16) * D + ac4 * 4);

    const int a_r = lane & 15;
    const int a_c = (lane >> 4) * 16;
    const int b_n = ((lane >> 4) << 3) + (lane & 7);
    const int b_c = ((lane >> 3) & 1) * 16;

    for (int kt = 0; kt < NCHUNK; kt++) {
        const int buf = kt & 1;

#pragma unroll
        for (int i = 0; i < 8; i++) {
            int r = ar + i * 16;
            __nv_bfloat162 lo = __floats2bfloat162_rn(av[i].x, av[i].y);
            __nv_bfloat162 hi = __floats2bfloat162_rn(av[i].z, av[i].w);
            uint2 p; p.x = *(uint32_t*)&lo; p.y = *(uint32_t*)&hi;
            *(uint2*)(pA[buf] + SWZ128((uint32_t)(r * 128 + ac4 * 8))) = p;
        }
        asm volatile("cp.async.wait_group 0;" ::: "memory");
        __syncthreads();

        if (kt + 1 < NCHUNK) {
            const int nb = buf ^ 1;
            const int k0 = (kt + 1) * CH;
#pragma unroll
            for (int i = 0; i < 8; i++) {
                int r = br + i * 32;
                uint32_t dst = sbB[nb] + SWZ128((uint32_t)(r * 128 + bc16 * 16));
                const __nv_bfloat16* src = Cg0 + (size_t)r * D + k0 + bc16 * 8;
                asm volatile("cp.async.cg.shared.global [%0], [%1], 16;" :: "r"(dst), "l"(src));
            }
            asm volatile("cp.async.commit_group;" ::: "memory");
#pragma unroll
            for (int i = 0; i < 8; i++)
                av[i] = *(const float4*)(Xg0 + (size_t)(ar + i * 16) * D + k0 + ac4 * 4);
        }

        const uint32_t aB = sbA[buf], bB = sbB[buf];
#pragma unroll
        for (int kk = 0; kk < 4; kk++) {
            uint32_t af[4][4], bfr[4][4];
#pragma unroll
            for (int mi = 0; mi < 4; mi++) {
                uint32_t addr = aB + SWZ128((uint32_t)((warpM * 64 + mi * 16 + a_r) * 128 + kk * 32 + a_c));
                asm volatile("ldmatrix.sync.aligned.m8n8.x4.shared.b16 {%0,%1,%2,%3}, [%4];"
                    : "=r"(af[mi][0]), "=r"(af[mi][1]), "=r"(af[mi][2]), "=r"(af[mi][3]) : "r"(addr));
            }
#pragma unroll
            for (int ng = 0; ng < 4; ng++) {
                uint32_t addr = bB + SWZ128((uint32_t)((warpN * 64 + ng * 16 + b_n) * 128 + kk * 32 + b_c));
                asm volatile("ldmatrix.sync.aligned.m8n8.x4.shared.b16 {%0,%1,%2,%3}, [%4];"
                    : "=r"(bfr[ng][0]), "=r"(bfr[ng][1]), "=r"(bfr[ng][2]), "=r"(bfr[ng][3]) : "r"(addr));
            }
#pragma unroll
            for (int mi = 0; mi < 4; mi++)
#pragma unroll
                for (int ng = 0; ng < 4; ng++) {
                    asm volatile("mma.sync.aligned.m16n8k16.row.col.f32.bf16.bf16.f32 "
                        "{%0,%1,%2,%3}, {%4,%5,%6,%7}, {%8,%9}, {%0,%1,%2,%3};"
                        : "+f"(acc[mi][2*ng][0]), "+f"(acc[mi][2*ng][1]),
                          "+f"(acc[mi][2*ng][2]), "+f"(acc[mi][2*ng][3])
                        : "r"(af[mi][0]), "r"(af[mi][1]), "r"(af[mi][2]), "r"(af[mi][3]),
                          "r"(bfr[ng][0]), "r"(bfr[ng][1]));
                    asm volatile("mma.sync.aligned.m16n8k16.row.col.f32.bf16.bf16.f32 "
                        "{%0,%1,%2,%3}, {%4,%5,%6,%7}, {%8,%9}, {%0,%1,%2,%3};"
                        : "+f"(acc[mi][2*ng+1][0]), "+f"(acc[mi][2*ng+1][1]),
                          "+f"(acc[mi][2*ng+1][2]), "+f"(acc[mi][2*ng+1][3])
                        : "r"(af[mi][0]), "r"(af[mi][1]), "r"(af[mi][2]), "r"(af[mi][3]),
                          "r"(bfr[ng][2]), "r"(bfr[ng][3]));
                }
        }
    }

    // ---- fused epilogue: per-CTA row argmin + candidate push ----
    __shared__ unsigned long long rowbest[TM];
    for (int i = tid; i < TM; i += 256) rowbest[i] = 0xFFFFFFFFFFFFFFFFull;
    __syncthreads();

    const int g = lane >> 2, t = lane & 3;
#pragma unroll
    for (int mi = 0; mi < 4; mi++) {
#pragma unroll
        for (int rr = 0; rr < 2; rr++) {
            int lrow = warpM * 64 + mi * 16 + rr * 8 + g;
            unsigned long long best = 0xFFFFFFFFFFFFFFFFull;
#pragma unroll
            for (int ni = 0; ni < 8; ni++) {
                int col = colBase + warpN * 64 + ni * 8 + 2 * t;
                float d0 = g_cnorm[col]     - 2.f * acc[mi][ni][rr * 2 + 0];
                float d1 = g_cnorm[col + 1] - 2.f * acc[mi][ni][rr * 2 + 1];
                unsigned long long k0 = make_key(d0, col);
                unsigned long long k1 = make_key(d1, col + 1);
                if (k0 < best) best = k0;
                if (k1 < best) best = k1;
            }
            atomicMin(&rowbest[lrow], best);
        }
    }
    __syncthreads();
    for (int i = tid; i < TM; i += 256)
        atomicMin(&g_best[rowBase + i], rowbest[i]);

#pragma unroll
    for (int mi = 0; mi < 4; mi++) {
#pragma unroll
        for (int rr = 0; rr < 2; rr++) {
            int lrow = warpM * 64 + mi * 16 + rr * 8 + g;
            int grow = rowBase + lrow;
            float thr = key_to_float(rowbest[lrow]) + MARGIN;
#pragma unroll
            for (int ni = 0; ni < 8; ni++) {
                int col = colBase + warpN * 64 + ni * 8 + 2 * t;
                float d0 = g_cnorm[col]     - 2.f * acc[mi][ni][rr * 2 + 0];
                float d1 = g_cnorm[col + 1] - 2.f * acc[mi][ni][rr * 2 + 1];
                if (d0 <= thr) {
                    int p = atomicAdd(&g_ccnt[grow], 1);
                    if (p < CAP) g_cand[(size_t)grow * CAP + p] = make_key(d0, col);
                }
                if (d1 <= thr) {
                    int p = atomicAdd(&g_ccnt[grow], 1);
                    if (p < CAP) g_cand[(size_t)grow * CAP + p] = make_key(d1, col + 1);
                }
            }
        }
    }
}

// ---------------- epilogue (R13-proven, 38.4us): resolve idx + gather/write, no X fast path ----------------
__global__ __launch_bounds__(128)
void epilogue_kernel(const float* __restrict__ X,
                     const float* __restrict__ C,
                     float* __restrict__ out) {
    __shared__ float ws[4];
    __shared__ int   cand[E];
    __shared__ int   ncand;
    __shared__ int   s_idx;

    const int row = blockIdx.x;
    const int tid = threadIdx.x;
    const int lane = tid & 31, wid = tid >> 5;

    const unsigned long long bk = g_best[row];
    const float gd = key_to_float(bk);
    const int gidx = (int)(bk & 0xffffffffull);
    const int cnt = g_ccnt[row];

    if (tid == 0) ncand = 0;
    __syncthreads();
    if (cnt > CAP) {
        for (int i = tid; i < E; i += 128) cand[i] = i;
        if (tid == 0) ncand = E;
    } else if (tid < cnt) {
        unsigned long long k = g_cand[(size_t)row * CAP + tid];
        if (key_to_float(k) <= gd + MARGIN) {
            int p = atomicAdd(&ncand, 1);
            cand[p] = (int)(k & 0xffffffffull);
        }
    }
    __syncthreads();
    const int n = ncand;

    if (n <= 1) {
        if (tid == 0) s_idx = gidx;
    } else {
        const float4* x4 = (const float4*)(X + (size_t)row * D);
        unsigned long long bestE = 0xFFFFFFFFFFFFFFFFull;
        for (int t = 0; t < n; t++) {
            int cidx = cand[t];
            const float4* c4 = (const float4*)(C + (size_t)cidx * D);
            float s = 0.f;
#pragma unroll
            for (int i = tid; i < D / 4; i += 128) {
                float4 xv = x4[i];
                float4 cv = c4[i];
                s += xv.x * cv.x + xv.y * cv.y + xv.z * cv.z + xv.w * cv.w;
            }
            for (int o = 16; o; o >>= 1) s += __shfl_down_sync(0xffffffffu, s, o);
            __syncthreads();
            if (lane == 0) ws[wid] = s;
            __syncthreads();
            if (tid == 0) {
                float dot = ws[0] + ws[1] + ws[2] + ws[3];
                float dist = g_cnorm[cidx] - 2.f * dot;
                unsigned long long kk = make_key(dist, cidx);
                bestE = (kk < bestE) ? kk : bestE;
            }
        }
        if (tid == 0) s_idx = (int)(bestE & 0xffffffffull);
    }
    __syncthreads();
    const int idx = s_idx;
    if (tid == 0) atomicAdd(&g_counts[idx], 1);

    // ---- gather + write (no X): quantized_st == C[idx] to 1 ulp ----
    const float4* c4 = (const float4*)(C + (size_t)idx * D);
    float* qo = out + OUT_Q_OFF + (size_t)row * D;
#pragma unroll
    for (int i = tid; i < D / 4; i += 128) {
        float4 v = c4[i];
        qo[i * 4 + 0] = v.x;
        qo[i * 4 + 1] = v.y;
        qo[i * 4 + 2] = v.z;
        qo[i * 4 + 3] = v.w;
    }

    float* enc = out + OUT_ENC_OFF + (size_t)row * E;
    if (tid == 0) {
        enc[0]   = (idx == 0)   ? 1.f : 0.f;
        enc[1]   = (idx == 1)   ? 1.f : 0.f;
        enc[510] = (idx == 510) ? 1.f : 0.f;
        enc[511] = (idx == 511) ? 1.f : 0.f;
    }
    for (int i = tid; i < 127; i += 128) {
        int kq = 2 + i * 4;
        float4 v = make_float4((idx == kq) ? 1.f : 0.f, (idx == kq + 1) ? 1.f : 0.f,
                               (idx == kq + 2) ? 1.f : 0.f, (idx == kq + 3) ? 1.f : 0.f);
        *(float4*)(enc + kq) = v;
    }
}

// ---------------- scalars: loss from g_best + xsum; perplexity ----------------
__global__ void scalars_kernel(float* __restrict__ out) {
    const int e = threadIdx.x;  // 512 threads
    float p = (float)g_counts[e] / (float)BROWS;
    float term = p * logf(p + 1e-10f);
    float ds = 0.f;
    for (int j = 0; j < 16; j++)
        ds += key_to_float(g_best[e + j * 512]);
    for (int o = 16; o; o >>= 1) {
        term += __shfl_down_sync(0xffffffffu, term, o);
        ds   += __shfl_down_sync(0xffffffffu, ds, o);
    }
    __shared__ float wt[16];
    __shared__ float wd[16];
    if ((e & 31) == 0) { wt[e >> 5] = term; wd[e >> 5] = ds; }
    __syncthreads();
    if (e == 0) {
        float H = 0.f; double DS = 0.0;
        for (int w = 0; w < 16; w++) { H += wt[w]; DS += (double)wd[w]; }
        out[0] = (float)(1.25 * ((g_xsum + DS) / (double)NQ));
        out[OUT_PERP_OFF] = expf(-H);
    }
}

// ---------------- launch ----------------
extern "C" void kernel_launch(void* const* d_in, const int* in_sizes, int n_in,
                              void* d_out, int out_size) {
    const float* X = (const float*)d_in[0];
    const float* C = (const float*)d_in[1];
    if (n_in >= 2 && in_sizes[0] == E * D && in_sizes[1] == BROWS * D) {
        const float* t = X; X = C; C = t;
    }
    float* out = (float*)d_out;

    static bool attr_done = false;
    if (!attr_done) {
        cudaFuncSetAttribute(gemm_mma_kernel,
                             cudaFuncAttributeMaxDynamicSharedMemorySize, GEMM_SMEM);
        attr_done = true;
    }

    init_kernel<<<BROWS / 256, 256>>>();
    convCnorm_kernel<<<E, 128>>>(C);
    gemm_mma_kernel<<<NGEMM + NXSUM, 256, GEMM_SMEM>>>(X);   // 148 blocks = one wave
    epilogue_kernel<<<BROWS, 128>>>(X, C, out);
    scalars_kernel<<<1, E>>>(out);
}